// round 13
// baseline (speedup 1.0000x reference)
#include <cuda_runtime.h>
#include <cstdint>

namespace {

constexpr int BATCH     = 20000;
constexpr int MTOT      = 49;
constexpr int KDIM      = 128;
constexpr int NDIM      = 128;
constexpr int TILE_ROWS = 128;
constexpr int NTILES    = 2;                      // row-tiles per CTA
constexpr int NTHREADS  = 512;

constexpr int PLANE      = 16384;                 // 128 rows x 128B = 64 fp16 k
constexpr int W_OFF      = 3 * PLANE;             // A triple-buffer ring first
constexpr int SMEM_TOTAL = W_OFF + 2 * PLANE;     // 48KB A ring + 32KB W = 81920 B

constexpr size_t ROW_STRIDE = (size_t)MTOT * KDIM;   // floats between batch rows

// SW128-style layout: smem row = 128B (64 fp16 k), 8 x 16B segs, seg' = seg^(row&7).
// ldmatrix.m8n8.x4.b16 -> m16n8k16 fp16 mma (mapping validated R5-R8).
// NEW: per-warp W fragments (N32 x K128 = 64 regs) hoisted once; mainloop has
// zero W-LDSM. Warp grid 4x4 (M32 x N32), 512 threads, 1 CTA/SM.

__device__ __forceinline__ uint32_t smem_u32(const void* p) {
    uint32_t a;
    asm("{ .reg .u64 t; cvta.to.shared.u64 t, %1; cvt.u32.u64 %0, t; }"
        : "=r"(a) : "l"(p));
    return a;
}

__device__ __forceinline__ uint32_t f16x2(float lo, float hi) {
    uint32_t r;                    // low half = lo (lower k index)
    asm("cvt.rn.f16x2.f32 %0, %2, %1;" : "=r"(r) : "f"(lo), "f"(hi));
    return r;
}

__device__ __forceinline__ void sts128(uint32_t addr, uint32_t a, uint32_t b,
                                       uint32_t c, uint32_t d) {
    asm volatile("st.shared.v4.b32 [%0], {%1, %2, %3, %4};"
                 :: "r"(addr), "r"(a), "r"(b), "r"(c), "r"(d) : "memory");
}

__device__ __forceinline__ void ldsm4(uint32_t& r0, uint32_t& r1,
                                      uint32_t& r2, uint32_t& r3, uint32_t addr) {
    asm volatile("ldmatrix.sync.aligned.m8n8.x4.shared.b16 {%0,%1,%2,%3}, [%4];"
                 : "=r"(r0), "=r"(r1), "=r"(r2), "=r"(r3) : "r"(addr));
}

__device__ __forceinline__ void mma_f16(float* c, uint32_t a0, uint32_t a1,
                                        uint32_t a2, uint32_t a3,
                                        uint32_t b0, uint32_t b1) {
    asm volatile(
        "mma.sync.aligned.m16n8k16.row.col.f32.f16.f16.f32 "
        "{%0,%1,%2,%3}, {%4,%5,%6,%7}, {%8,%9}, {%0,%1,%2,%3};"
        : "+f"(c[0]), "+f"(c[1]), "+f"(c[2]), "+f"(c[3])
        : "r"(a0), "r"(a1), "r"(a2), "r"(a3), "r"(b0), "r"(b1));
}

__global__ void __launch_bounds__(NTHREADS, 1)
so3_linear_kernel(const float* __restrict__ in,
                  const float* __restrict__ w,
                  const float* __restrict__ bias,
                  float* __restrict__ out)
{
    extern __shared__ char smem[];
    const uint32_t sb = smem_u32(smem);

    const int tid  = threadIdx.x;
    const int lane = tid & 31;
    const int wid  = tid >> 5;
    const int g    = lane >> 2;
    const int t    = lane & 3;

    const int m = blockIdx.y;
    int l = 0;
    while ((l + 1) * (l + 1) <= m) l++;
    const float* wl = w + (size_t)l * NDIM * KDIM;

    // ---- producer mapping: 8 threads/row, rows prow & prow+64 ----
    const int prow = tid >> 3;               // 0..63
    const int seg  = tid & 7;
    const uint32_t stsOff0 = (uint32_t)(prow * 128 + ((seg ^ (prow & 7)) << 4));

    const int rowBase0 = blockIdx.x * (NTILES * TILE_ROWS);
    const int nt = min(NTILES, (BATCH - rowBase0 + TILE_ROWS - 1) / TILE_ROWS);
    const int nplanes = nt * 2;

    const float* aCol = in + (size_t)m * KDIM + seg * 8;

    float st[2][8];                           // staged fp32 for one plane

    auto ldgPlane = [&](int p) {
        if (p >= nplanes) return;
        const int tl = p >> 1, h = p & 1;
        #pragma unroll
        for (int i = 0; i < 2; i++) {
            int r = rowBase0 + tl * TILE_ROWS + prow + 64 * i;
            if (r >= BATCH) r = BATCH - 1;   // clamped rows never stored
            const float* q = aCol + (size_t)r * ROW_STRIDE + h * 64;
            float4 q0 = *reinterpret_cast<const float4*>(q);
            float4 q1 = *reinterpret_cast<const float4*>(q + 4);
            st[i][0] = q0.x; st[i][1] = q0.y; st[i][2] = q0.z; st[i][3] = q0.w;
            st[i][4] = q1.x; st[i][5] = q1.y; st[i][6] = q1.z; st[i][7] = q1.w;
        }
    };
    auto stsPlane = [&](int p) {
        if (p >= nplanes) return;
        const uint32_t ad = sb + (uint32_t)((p % 3) * PLANE) + stsOff0;
        #pragma unroll
        for (int i = 0; i < 2; i++)
            sts128(ad + i * 8192,
                   f16x2(st[i][0], st[i][1]), f16x2(st[i][2], st[i][3]),
                   f16x2(st[i][4], st[i][5]), f16x2(st[i][6], st[i][7]));
    };

    // ---- prologue: A plane0 staged, plane1 in regs; W staged ----
    ldgPlane(0);
    stsPlane(0);
    ldgPlane(1);

    {   // W: 128 n-rows x 128 k fp16, 2 planes of k64; rows prow, prow+64
        const float* wRow = wl + (size_t)prow * KDIM + seg * 8;
        #pragma unroll
        for (int h = 0; h < 2; h++) {
            const uint32_t wb = sb + (uint32_t)(W_OFF + h * PLANE) + stsOff0;
            #pragma unroll
            for (int i = 0; i < 2; i++) {
                const float* q = wRow + (size_t)i * (64 * KDIM) + h * 64;
                float4 q0 = *reinterpret_cast<const float4*>(q);
                float4 q1 = *reinterpret_cast<const float4*>(q + 4);
                sts128(wb + i * 8192,
                       f16x2(q0.x, q0.y), f16x2(q0.z, q0.w),
                       f16x2(q1.x, q1.y), f16x2(q1.z, q1.w));
            }
        }
    }
    __syncthreads();

    // ---- consumer mapping: warp grid 4 rows x 4 cols (M32, N32 per warp) ----
    const int warp_row = (wid & 3) * 32;
    const int warp_col = (wid >> 2) * 32;
    const int x7 = lane & 7;
    const int aRowOff = ((lane >> 3) & 1) * 8 + x7;
    const int aSh     = lane >> 4;
    const int bRowOff = ((lane >> 4) & 1) * 8 + x7;
    const int bSh     = (lane >> 3) & 1;
    const uint32_t aBaseOff = (uint32_t)((warp_row + aRowOff) * 128);
    uint32_t aSegT[4], bSegT[4];
    #pragma unroll
    for (int ks = 0; ks < 4; ks++) {
        aSegT[ks] = (uint32_t)(((2 * ks + aSh) ^ x7) << 4);
        bSegT[ks] = (uint32_t)(((2 * ks + bSh) ^ x7) << 4);
    }

    // ---- hoist W fragments: N32 x K128 = 64 regs, loaded once ----
    uint32_t wf[64];
    #pragma unroll
    for (int ks = 0; ks < 8; ks++) {
        const int h = ks >> 2, ksl = ks & 3;
        const uint32_t wb = sb + (uint32_t)(W_OFF + h * PLANE);
        #pragma unroll
        for (int np = 0; np < 2; np++) {
            const uint32_t ad = wb +
                (uint32_t)((warp_col + np * 16 + bRowOff) * 128) + bSegT[ksl];
            ldsm4(wf[ks * 8 + np * 4 + 0], wf[ks * 8 + np * 4 + 1],
                  wf[ks * 8 + np * 4 + 2], wf[ks * 8 + np * 4 + 3], ad);
        }
    }
    __syncthreads();   // W smem dead; A slot writes may proceed next iteration

    float acc[2][4][4] = {};
    const bool addb = (m == 0);

    for (int p = 0; p < nplanes; p++) {
        stsPlane(p + 1);                     // slot (p+1)%3, free since p-2
        ldgPlane(p + 2);

        const int hks = (p & 1) * 4;         // global ks base for this plane
        const uint32_t Ab = sb + (uint32_t)((p % 3) * PLANE) + aBaseOff;

        #pragma unroll
        for (int ksl = 0; ksl < 4; ksl++) {
            uint32_t af[4], ag[4];
            ldsm4(af[0], af[1], af[2], af[3], Ab + aSegT[ksl]);
            ldsm4(ag[0], ag[1], ag[2], ag[3], Ab + 2048 + aSegT[ksl]);
            const int kb = (hks + ksl) * 8;
            #pragma unroll
            for (int ni = 0; ni < 4; ni++) {
                mma_f16(acc[0][ni], af[0], af[1], af[2], af[3],
                        wf[kb + 2 * ni], wf[kb + 2 * ni + 1]);
                mma_f16(acc[1][ni], ag[0], ag[1], ag[2], ag[3],
                        wf[kb + 2 * ni], wf[kb + 2 * ni + 1]);
            }
        }

        if (p & 1) {
            // ---- epilogue for tile p>>1 ----
            const int rb = rowBase0 + (p >> 1) * TILE_ROWS;
            #pragma unroll
            for (int mi = 0; mi < 2; mi++) {
                #pragma unroll
                for (int ni = 0; ni < 4; ni++) {
                    const int cc = warp_col + ni * 8 + 2 * t;
                    const int r0 = rb + warp_row + mi * 16 + g;
                    float2 v0 = make_float2(acc[mi][ni][0], acc[mi][ni][1]);
                    float2 v1 = make_float2(acc[mi][ni][2], acc[mi][ni][3]);
                    if (addb) {
                        const float b0v = bias[cc], b1v = bias[cc + 1];
                        v0.x += b0v; v0.y += b1v;
                        v1.x += b0v; v1.y += b1v;
                    }
                    if (r0 < BATCH)
                        *reinterpret_cast<float2*>(out + (((size_t)r0 * MTOT + m) * NDIM + cc)) = v0;
                    if (r0 + 8 < BATCH)
                        *reinterpret_cast<float2*>(out + (((size_t)(r0 + 8) * MTOT + m) * NDIM + cc)) = v1;
                    acc[mi][ni][0] = 0.f; acc[mi][ni][1] = 0.f;
                    acc[mi][ni][2] = 0.f; acc[mi][ni][3] = 0.f;
                }
            }
        }
        __syncthreads();
    }
}

}  // namespace

extern "C" void kernel_launch(void* const* d_in, const int* in_sizes, int n_in,
                              void* d_out, int out_size) {
    (void)in_sizes; (void)n_in; (void)out_size;
    const float* in   = (const float*)d_in[0];
    const float* w    = (const float*)d_in[1];
    const float* bias = (const float*)d_in[2];
    float* out        = (float*)d_out;

    cudaFuncSetAttribute(so3_linear_kernel,
                         cudaFuncAttributeMaxDynamicSharedMemorySize, SMEM_TOTAL);

    dim3 grid((BATCH + NTILES * TILE_ROWS - 1) / (NTILES * TILE_ROWS), MTOT);
    so3_linear_kernel<<<grid, NTHREADS, SMEM_TOTAL>>>(in, w, bias, out);
}

// round 14
// speedup vs baseline: 1.6407x; 1.6407x over previous
#include <cuda_runtime.h>
#include <cstdint>

namespace {

constexpr int BATCH     = 20000;
constexpr int MTOT      = 49;
constexpr int KDIM      = 128;
constexpr int NDIM      = 128;
constexpr int TILE_ROWS = 128;
constexpr int NTILES    = 4;                      // row-tiles per CTA (best: R8)
constexpr int NTHREADS  = 256;

constexpr int PLANE      = 16384;                 // 128 rows x 128B = 64 fp16 k
constexpr int W_OFF      = 4 * PLANE;             // A 4-deep ring first
constexpr int SMEM_TOTAL = W_OFF + 2 * PLANE;     // 64KB A + 32KB W = 98304 B

constexpr size_t ROW_STRIDE = (size_t)MTOT * KDIM;   // floats between batch rows

// SW128-style layout: smem row = 128B (64 fp16 k), 8 x 16B segs, seg' = seg^(row&7).
// Consumer: ldmatrix.m8n8.x4.b16 -> m16n8k16 fp16 mma (mapping validated R5-R8).
// R14: 4-deep A ring lets the producer run one full plane ahead, so __syncthreads
// fires only after every SECOND plane (half of R8's barrier count).

__device__ __forceinline__ uint32_t smem_u32(const void* p) {
    uint32_t a;
    asm("{ .reg .u64 t; cvta.to.shared.u64 t, %1; cvt.u32.u64 %0, t; }"
        : "=r"(a) : "l"(p));
    return a;
}

__device__ __forceinline__ uint32_t f16x2(float lo, float hi) {
    uint32_t r;                    // low half = lo (lower k index)
    asm("cvt.rn.f16x2.f32 %0, %2, %1;" : "=r"(r) : "f"(lo), "f"(hi));
    return r;
}

__device__ __forceinline__ void sts128(uint32_t addr, uint32_t a, uint32_t b,
                                       uint32_t c, uint32_t d) {
    asm volatile("st.shared.v4.b32 [%0], {%1, %2, %3, %4};"
                 :: "r"(addr), "r"(a), "r"(b), "r"(c), "r"(d) : "memory");
}

__device__ __forceinline__ void ldsm4(uint32_t& r0, uint32_t& r1,
                                      uint32_t& r2, uint32_t& r3, uint32_t addr) {
    asm volatile("ldmatrix.sync.aligned.m8n8.x4.shared.b16 {%0,%1,%2,%3}, [%4];"
                 : "=r"(r0), "=r"(r1), "=r"(r2), "=r"(r3) : "r"(addr));
}

__device__ __forceinline__ void mma_f16(float* c, uint32_t a0, uint32_t a1,
                                        uint32_t a2, uint32_t a3,
                                        uint32_t b0, uint32_t b1) {
    asm volatile(
        "mma.sync.aligned.m16n8k16.row.col.f32.f16.f16.f32 "
        "{%0,%1,%2,%3}, {%4,%5,%6,%7}, {%8,%9}, {%0,%1,%2,%3};"
        : "+f"(c[0]), "+f"(c[1]), "+f"(c[2]), "+f"(c[3])
        : "r"(a0), "r"(a1), "r"(a2), "r"(a3), "r"(b0), "r"(b1));
}

__global__ void __launch_bounds__(NTHREADS, 2)
so3_linear_kernel(const float* __restrict__ in,
                  const float* __restrict__ w,
                  const float* __restrict__ bias,
                  float* __restrict__ out)
{
    extern __shared__ char smem[];
    const uint32_t sb = smem_u32(smem);

    const int tid  = threadIdx.x;
    const int lane = tid & 31;
    const int wid  = tid >> 5;
    const int g    = lane >> 2;
    const int t    = lane & 3;

    const int m = blockIdx.y;
    int l = 0;
    while ((l + 1) * (l + 1) <= m) l++;
    const float* wl = w + (size_t)l * NDIM * KDIM;

    // ---- producer mapping: 8 threads/row, each 32B fp32 -> 16B fp16 seg ----
    const int prow = tid >> 3;               // 0..31 (+32*i covers 128 rows)
    const int seg  = tid & 7;
    const uint32_t stsOff0 = (uint32_t)(prow * 128 + ((seg ^ (prow & 7)) << 4));

    const int rowBase0 = blockIdx.x * (NTILES * TILE_ROWS);
    const int nt = min(NTILES, (BATCH - rowBase0 + TILE_ROWS - 1) / TILE_ROWS);
    const int nplanes = nt * 2;              // k64 planes

    const float* aCol = in + (size_t)m * KDIM + seg * 8;

    float st[4][8];                           // staged fp32 for one plane

    auto ldgPlane = [&](int p) {
        if (p >= nplanes) return;
        const int tl = p >> 1, h = p & 1;
        #pragma unroll
        for (int i = 0; i < 4; i++) {
            int r = rowBase0 + tl * TILE_ROWS + prow + 32 * i;
            if (r >= BATCH) r = BATCH - 1;   // clamped rows never stored
            const float* q = aCol + (size_t)r * ROW_STRIDE + h * 64;
            float4 q0 = *reinterpret_cast<const float4*>(q);
            float4 q1 = *reinterpret_cast<const float4*>(q + 4);
            st[i][0] = q0.x; st[i][1] = q0.y; st[i][2] = q0.z; st[i][3] = q0.w;
            st[i][4] = q1.x; st[i][5] = q1.y; st[i][6] = q1.z; st[i][7] = q1.w;
        }
    };
    auto stsPlane = [&](int p) {
        if (p >= nplanes) return;
        const uint32_t ad = sb + (uint32_t)((p & 3) * PLANE) + stsOff0;
        #pragma unroll
        for (int i = 0; i < 4; i++)
            sts128(ad + i * 4096,
                   f16x2(st[i][0], st[i][1]), f16x2(st[i][2], st[i][3]),
                   f16x2(st[i][4], st[i][5]), f16x2(st[i][6], st[i][7]));
    };

    // ---- prologue: planes 0,1 staged; plane 2 in regs; W staged ----
    ldgPlane(0); stsPlane(0);
    ldgPlane(1); stsPlane(1);
    ldgPlane(2);

    {   // W: 128 n-rows x 128 k fp16, 2 planes of k64
        const float* wRow = wl + (size_t)prow * KDIM + seg * 8;
        #pragma unroll
        for (int p = 0; p < 2; p++) {
            const uint32_t wb = sb + (uint32_t)(W_OFF + p * PLANE) + stsOff0;
            #pragma unroll
            for (int i = 0; i < 4; i++) {
                const float* q = wRow + i * (32 * KDIM) + p * 64;
                float4 q0 = *reinterpret_cast<const float4*>(q);
                float4 q1 = *reinterpret_cast<const float4*>(q + 4);
                sts128(wb + i * 4096,
                       f16x2(q0.x, q0.y), f16x2(q0.z, q0.w),
                       f16x2(q1.x, q1.y), f16x2(q1.z, q1.w));
            }
        }
    }
    __syncthreads();

    // ---- consumer mapping (validated R5-R8) ----
    const int warp_row = (wid & 3) * 32;
    const int warp_col = (wid >> 2) * 64;
    const int x7 = lane & 7;
    const int aRowOff = ((lane >> 3) & 1) * 8 + x7;
    const int aSh     = lane >> 4;
    const int bRowOff = ((lane >> 4) & 1) * 8 + x7;
    const int bSh     = (lane >> 3) & 1;
    const uint32_t aBaseOff = (uint32_t)((warp_row + aRowOff) * 128);
    const uint32_t bBaseOff = (uint32_t)((warp_col + bRowOff) * 128);
    uint32_t aSegT[4], bSegT[4];
    #pragma unroll
    for (int ks = 0; ks < 4; ks++) {
        aSegT[ks] = (uint32_t)(((2 * ks + aSh) ^ x7) << 4);
        bSegT[ks] = (uint32_t)(((2 * ks + bSh) ^ x7) << 4);
    }

    float acc[2][8][4] = {};
    const bool addb = (m == 0);

    for (int gj = 0; gj < nplanes; gj++) {
        const int h = gj & 1;

        // producer runs one plane ahead: STS(gj+2) (loaded at gj-1), LDG(gj+3)
        stsPlane(gj + 2);
        ldgPlane(gj + 3);

        const uint32_t Ab = sb + (uint32_t)((gj & 3) * PLANE) + aBaseOff;
        const uint32_t Wb = sb + (uint32_t)(W_OFF + h * PLANE) + bBaseOff;

        #pragma unroll
        for (int ks = 0; ks < 4; ks++) {               // 4 x k16 = k64
            uint32_t af[4], ag[4];
            ldsm4(af[0], af[1], af[2], af[3], Ab + aSegT[ks]);
            ldsm4(ag[0], ag[1], ag[2], ag[3], Ab + 2048 + aSegT[ks]);
            #pragma unroll
            for (int np = 0; np < 4; np++) {
                uint32_t b0, b1, b2, b3;
                ldsm4(b0, b1, b2, b3, Wb + (uint32_t)(np * 2048) + bSegT[ks]);
                mma_f16(acc[0][2 * np],     af[0], af[1], af[2], af[3], b0, b1);
                mma_f16(acc[0][2 * np + 1], af[0], af[1], af[2], af[3], b2, b3);
                mma_f16(acc[1][2 * np],     ag[0], ag[1], ag[2], ag[3], b0, b1);
                mma_f16(acc[1][2 * np + 1], ag[0], ag[1], ag[2], ag[3], b2, b3);
            }
        }

        if (h == 1) {
            // ---- epilogue for tile gj>>1, then the (only) barrier ----
            const int rb = rowBase0 + (gj >> 1) * TILE_ROWS;
            #pragma unroll
            for (int mi = 0; mi < 2; mi++) {
                #pragma unroll
                for (int ni = 0; ni < 8; ni++) {
                    const int cc = warp_col + ni * 8 + 2 * t;
                    const int r0 = rb + warp_row + mi * 16 + g;
                    float2 v0 = make_float2(acc[mi][ni][0], acc[mi][ni][1]);
                    float2 v1 = make_float2(acc[mi][ni][2], acc[mi][ni][3]);
                    if (addb) {
                        const float b0v = bias[cc], b1v = bias[cc + 1];
                        v0.x += b0v; v0.y += b1v;
                        v1.x += b0v; v1.y += b1v;
                    }
                    if (r0 < BATCH)
                        *reinterpret_cast<float2*>(out + (((size_t)r0 * MTOT + m) * NDIM + cc)) = v0;
                    if (r0 + 8 < BATCH)
                        *reinterpret_cast<float2*>(out + (((size_t)(r0 + 8) * MTOT + m) * NDIM + cc)) = v1;
                    acc[mi][ni][0] = 0.f; acc[mi][ni][1] = 0.f;
                    acc[mi][ni][2] = 0.f; acc[mi][ni][3] = 0.f;
                }
            }
            __syncthreads();                  // one barrier per 2 planes (k128)
        }
    }
}

}  // namespace

extern "C" void kernel_launch(void* const* d_in, const int* in_sizes, int n_in,
                              void* d_out, int out_size) {
    (void)in_sizes; (void)n_in; (void)out_size;
    const float* in   = (const float*)d_in[0];
    const float* w    = (const float*)d_in[1];
    const float* bias = (const float*)d_in[2];
    float* out        = (float*)d_out;

    cudaFuncSetAttribute(so3_linear_kernel,
                         cudaFuncAttributeMaxDynamicSharedMemorySize, SMEM_TOTAL);

    dim3 grid((BATCH + NTILES * TILE_ROWS - 1) / (NTILES * TILE_ROWS), MTOT);
    so3_linear_kernel<<<grid, NTHREADS, SMEM_TOTAL>>>(in, w, bias, out);
}